// round 16
// baseline (speedup 1.0000x reference)
#include <cuda_runtime.h>
#include <cuda_bf16.h>
#include <math.h>
#include <stdint.h>

#define N_NODES 12800
#define N_EDGES 128000
#define G 64
#define NPG 200
#define LMD 1024
#define H 128
#define NT 42
#define HOPS 5
#define NCH4 4
#define CHL (LMD / NCH4)

// ---- k_bil smem: quarter-range A fragments + raw B stages ----
#define AFRAG_Q (4 * 4 * 32 * 4)     // 2048 u32 (4 steps worth)
#define RSTR 132
#define RSTAGE (16 * RSTR)
#define NSTAGE 4
#define BIL_SMEM ((2 * AFRAG_Q + NSTAGE * RSTAGE) * 4)   // 50176 B

// ---- k_nodes0 smem ----
#define ASTR 68
#define BSTR 132
#define ASIZE (64 * ASTR)
#define BSIZE (64 * BSTR)
#define SMEM_BYTES ((2 * ASIZE + 2 * BSIZE) * 4)  // 102400

#define LTM 32

// ---------------- static scratch ----------------
__device__ __align__(16) float d_P[(size_t)NCH4 * H * G * H];
__device__ __align__(16) float d_Pc[(size_t)NCH4 * G * H];
__device__ __align__(16) float d_nodes[(size_t)N_NODES * H];
__device__ __align__(16) float d_hbuf[(size_t)N_NODES * H];
__device__ __align__(16) uint32_t d_lmBig[G * 512];
__device__ __align__(16) uint32_t d_lmSml[G * 512];
__device__ __align__(16) uint32_t d_linBig[HOPS * 64 * H];
__device__ __align__(16) uint32_t d_linSml[HOPS * 64 * H];
__device__ __align__(16) uint32_t d_MTBig[G * 64 * H];
__device__ __align__(16) uint32_t d_MTSml[G * 64 * H];
__device__ float d_asrc[N_NODES];
__device__ float d_adst[N_NODES];
__device__ float d_aet[HOPS * NT];
__device__ float d_lscr[N_EDGES];
__device__ int d_deg[N_NODES];
__device__ int d_rowptr[N_NODES + 1];
__device__ int d_cursor[N_NODES];
__device__ int d_csr[N_EDGES];

__device__ __forceinline__ float lrelu(float x) { return x > 0.f ? x : 0.2f * x; }
__device__ __forceinline__ float gelu_exact(float x) {
    return 0.5f * x * (1.f + erff(x * 0.70710678118654752440f));
}

__device__ __forceinline__ uint32_t bpack(float e, float o) {
    __nv_bfloat162 p = __floats2bfloat162_rn(e, o);
    return *reinterpret_cast<uint32_t*>(&p);
}
__device__ __forceinline__ float bbig(float x) {
    return __bfloat162float(__float2bfloat16_rn(x));
}
__device__ __forceinline__ void bsplit2(float v0, float v1, uint32_t& big, uint32_t& sml) {
    float b0 = bbig(v0), b1 = bbig(v1);
    big = bpack(b0, b1);
    sml = bpack(v0 - b0, v1 - b1);
}

__device__ __forceinline__ void cp16(uint32_t saddr, const void* gptr) {
    asm volatile("cp.async.ca.shared.global [%0], [%1], 16;" :: "r"(saddr), "l"(gptr));
}
__device__ __forceinline__ void cp_commit() { asm volatile("cp.async.commit_group;"); }
__device__ __forceinline__ void cp_wait2() { asm volatile("cp.async.wait_group 2;"); }

#define MMA4(C, A0, A1, A2, A3, B0, B1)                                     \
    asm volatile(                                                           \
        "mma.sync.aligned.m16n8k16.row.col.f32.bf16.bf16.f32 "              \
        "{%0,%1,%2,%3}, {%4,%5,%6,%7}, {%8,%9}, {%0,%1,%2,%3};"             \
        : "+f"(C[0]), "+f"(C[1]), "+f"(C[2]), "+f"(C[3])                    \
        : "r"(A0), "r"(A1), "r"(A2), "r"(A3), "r"(B0), "r"(B1));

// one K16 step with array-layout A/B in smem (k_nodes0)
__device__ __forceinline__ void mma_step(const uint32_t* As_h, const uint32_t* As_l,
                                         const uint32_t* Bs_h, const uint32_t* Bs_l,
                                         float acc[4][2][4], int g, int t, int n0, int ps) {
    uint32_t bh[2][2], bl[2][2];
#pragma unroll
    for (int nt = 0; nt < 2; nt++) {
        int col = n0 + nt * 8 + g;
        bh[nt][0] = Bs_h[(ps + t) * BSTR + col];
        bh[nt][1] = Bs_h[(ps + t + 4) * BSTR + col];
        bl[nt][0] = Bs_l[(ps + t) * BSTR + col];
        bl[nt][1] = Bs_l[(ps + t + 4) * BSTR + col];
    }
#pragma unroll
    for (int mt = 0; mt < 4; mt++) {
        int r0 = (mt * 16 + g) * ASTR, r1 = (mt * 16 + 8 + g) * ASTR;
        uint32_t ah0 = As_h[r0 + ps + t];
        uint32_t ah1 = As_h[r1 + ps + t];
        uint32_t ah2 = As_h[r0 + ps + t + 4];
        uint32_t ah3 = As_h[r1 + ps + t + 4];
        uint32_t al0 = As_l[r0 + ps + t];
        uint32_t al1 = As_l[r1 + ps + t];
        uint32_t al2 = As_l[r0 + ps + t + 4];
        uint32_t al3 = As_l[r1 + ps + t + 4];
#pragma unroll
        for (int nt = 0; nt < 2; nt++) {
            MMA4(acc[mt][nt], ah0, ah1, ah2, ah3, bh[nt][0], bh[nt][1]);
            MMA4(acc[mt][nt], al0, al1, al2, al3, bh[nt][0], bh[nt][1]);
            MMA4(acc[mt][nt], ah0, ah1, ah2, ah3, bl[nt][0], bl[nt][1]);
        }
    }
}

// ---------------- branch-A prep: lm split ----------------
__global__ void k_prepA(const float* __restrict__ lm) {
    int id = blockIdx.x * 256 + threadIdx.x;
    int r = id >> 9, p = id & 511;
    float2 v = *(const float2*)&lm[(size_t)r * LMD + 2 * p];
    uint32_t bb, s;
    bsplit2(v.x, v.y, bb, s);
    d_lmBig[r * 512 + p] = bb;
    d_lmSml[r * 512 + p] = s;
}

// ---------------- branch-B prep: lin split + deg zero ----------------
__global__ void k_prepB(const float* __restrict__ glin) {
    int b = blockIdx.x;
    int tid = threadIdx.x;
    if (b < 160) {
        int id = b * 256 + tid;
        int hop = id >> 13, rem = id & 8191;
        int kp = rem >> 7, h = rem & 127;
        const float* L = glin + (size_t)hop * H * H;
        float v0 = L[(size_t)(2 * kp) * H + h];
        float v1 = L[(size_t)(2 * kp + 1) * H + h];
        uint32_t bb, s;
        bsplit2(v0, v1, bb, s);
        d_linBig[id] = bb;
        d_linSml[id] = s;
    } else {
        int i = (b - 160) * 256 + tid;
        if (i < N_NODES) d_deg[i] = 0;
    }
}

// ---------------- CSR build ----------------
__global__ void k_count(const int* __restrict__ ei) {
    int e = blockIdx.x * blockDim.x + threadIdx.x;
    if (e < N_EDGES) atomicAdd(&d_deg[ei[N_EDGES + e]], 1);
}

__global__ void k_scan() {
    __shared__ int sums[1024];
    const int CH = 13;
    int t = threadIdx.x;
    int base = t * CH;
    int loc[CH];
    int s = 0;
#pragma unroll
    for (int j = 0; j < CH; j++) {
        int idx = base + j;
        int v = (idx < N_NODES) ? d_deg[idx] : 0;
        loc[j] = v;
        s += v;
    }
    sums[t] = s;
    __syncthreads();
    for (int off = 1; off < 1024; off <<= 1) {
        int v = (t >= off) ? sums[t - off] : 0;
        __syncthreads();
        sums[t] += v;
        __syncthreads();
    }
    int run = (t > 0) ? sums[t - 1] : 0;
#pragma unroll
    for (int j = 0; j < CH; j++) {
        int idx = base + j;
        if (idx < N_NODES) {
            d_rowptr[idx] = run;
            d_cursor[idx] = run;
            run += loc[j];
        }
    }
    if (t == 0) d_rowptr[N_NODES] = N_EDGES;
}

__global__ void k_scatter(const int* __restrict__ ei, const int* __restrict__ et) {
    int e = blockIdx.x * blockDim.x + threadIdx.x;
    if (e < N_EDGES) {
        int d = ei[N_EDGES + e];
        int pos = atomicAdd(&d_cursor[d], 1);
        d_csr[pos] = ei[e] | (et[e] << 20);
    }
}

// ---------------- bilinear + ctx: 4-stage pipeline, quarter A refill -------
__global__ void __launch_bounds__(256, 3) k_bil(const float* __restrict__ W,
                                                const float* __restrict__ Wlm) {
    extern __shared__ uint32_t su[];
    uint32_t* Af_h = su;
    uint32_t* Af_l = su + AFRAG_Q;
    float* raw = (float*)(su + 2 * AFRAG_Q);
    uint32_t raw_s = (uint32_t)__cvta_generic_to_shared(raw);

    int k = blockIdx.x, ch = blockIdx.y;
    int tid = threadIdx.x;
    int lane = tid & 31, wid = tid >> 5;
    int g = lane >> 2, t = lane & 3, n0 = wid * 16;

    const float* Bg = (k < H) ? (W + ((size_t)k * LMD + (size_t)ch * CHL) * H)
                              : (Wlm + (size_t)(ch * CHL) * H);

    // prologue: B stages 0,1,2
#pragma unroll
    for (int s = 0; s < NSTAGE - 1; s++) {
#pragma unroll
        for (int i = 0; i < 2; i++) {
            int id = tid + 256 * i;
            int row = id >> 5, c4 = id & 31;
            cp16(raw_s + (s * RSTAGE + row * RSTR + c4 * 4) * 4,
                 Bg + (size_t)(s * 16 + row) * H + c4 * 4);
        }
        cp_commit();
    }

    float acc[4][2][4];
#pragma unroll
    for (int a = 0; a < 4; a++)
#pragma unroll
        for (int b = 0; b < 2; b++)
#pragma unroll
            for (int c = 0; c < 4; c++) acc[a][b][c] = 0.f;

#pragma unroll 1
    for (int q = 0; q < 4; q++) {
        // A fragments for this quarter (prev quarter's reads done at trailing sync)
#pragma unroll
        for (int it = 0; it < 8; it++) {
            int id = tid + 256 * it;
            int r = id >> 5, p = id & 31;
            int stepL = p >> 3, tt = p & 3, h4 = (p >> 2) & 1;
            int gg = r & 7, hb = (r >> 3) & 1, mt = r >> 4;
            int slot = ((stepL * 4 + mt) * 32 + gg * 4 + tt) * 4 + h4 * 2 + hb;
            int P = q * 32 + p;
            Af_h[slot] = d_lmBig[r * 512 + ch * 128 + P];
            Af_l[slot] = d_lmSml[r * 512 + ch * 128 + P];
        }
#pragma unroll 1
        for (int stepL = 0; stepL < 4; stepL++) {
            int step = q * 4 + stepL;
            cp_wait2();
            __syncthreads();
            if (step + NSTAGE - 1 < 16) {
                int s = step + NSTAGE - 1;
                int buf = s % NSTAGE;
#pragma unroll
                for (int i = 0; i < 2; i++) {
                    int id = tid + 256 * i;
                    int row = id >> 5, c4 = id & 31;
                    cp16(raw_s + (buf * RSTAGE + row * RSTR + c4 * 4) * 4,
                         Bg + (size_t)(s * 16 + row) * H + c4 * 4);
                }
            }
            cp_commit();

            const float* rb = raw + (step % NSTAGE) * RSTAGE;
            uint32_t bh[2][2], bl[2][2];
#pragma unroll
            for (int nt = 0; nt < 2; nt++) {
                int col = n0 + nt * 8 + g;
                bsplit2(rb[(2 * t) * RSTR + col], rb[(2 * t + 1) * RSTR + col],
                        bh[nt][0], bl[nt][0]);
                bsplit2(rb[(2 * t + 8) * RSTR + col], rb[(2 * t + 9) * RSTR + col],
                        bh[nt][1], bl[nt][1]);
            }
#pragma unroll
            for (int mt = 0; mt < 4; mt++) {
                uint4 ah = *(const uint4*)&Af_h[((stepL * 4 + mt) * 32 + lane) * 4];
                uint4 al = *(const uint4*)&Af_l[((stepL * 4 + mt) * 32 + lane) * 4];
#pragma unroll
                for (int nt = 0; nt < 2; nt++) {
                    MMA4(acc[mt][nt], ah.x, ah.y, ah.z, ah.w, bh[nt][0], bh[nt][1]);
                    MMA4(acc[mt][nt], al.x, al.y, al.z, al.w, bh[nt][0], bh[nt][1]);
                    MMA4(acc[mt][nt], ah.x, ah.y, ah.z, ah.w, bl[nt][0], bl[nt][1]);
                }
            }
            __syncthreads();
        }
    }

    float* Pp = (k < H) ? (d_P + ((size_t)(ch * H + k) * G) * H)
                        : (d_Pc + (size_t)ch * G * H);
#pragma unroll
    for (int mt = 0; mt < 4; mt++) {
        int row = mt * 16 + g;
#pragma unroll
        for (int nt = 0; nt < 2; nt++) {
            int col = n0 + nt * 8 + 2 * t;
            *(float2*)&Pp[(size_t)row * H + col] = make_float2(acc[mt][nt][0], acc[mt][nt][1]);
            *(float2*)&Pp[(size_t)(row + 8) * H + col] = make_float2(acc[mt][nt][2], acc[mt][nt][3]);
        }
    }
}

// reduce chunks + transpose + split to MT bf16 pairs [g][hp][k]
__global__ void k_redT() {
    __shared__ float tile[32][33];
    int g = blockIdx.x, kt = blockIdx.y, ht = blockIdx.z;
    int tx = threadIdx.x, ty = threadIdx.y;
    int k = kt * 32 + ty, h = ht * 32 + tx;
    size_t base = ((size_t)k * G + g) * H + h;
    float s = 0.f;
#pragma unroll
    for (int c = 0; c < NCH4; c++) s += d_P[(size_t)c * H * G * H + base];
    tile[ty][tx] = s;
    __syncthreads();
    if (ty < 16) {
        float v0 = tile[tx][2 * ty];
        float v1 = tile[tx][2 * ty + 1];
        uint32_t b, sm;
        bsplit2(v0, v1, b, sm);
        int idx = (g * 64 + ht * 16 + ty) * H + kt * 32 + tx;
        d_MTBig[idx] = b;
        d_MTSml[idx] = sm;
    }
}

// ---------------- nodes init (ctx summed inline) ----------------
__global__ void __launch_bounds__(256) k_nodes0(const float* __restrict__ nemb,
                                                const float* __restrict__ bbil,
                                                const float* __restrict__ blm) {
    extern __shared__ uint32_t smem_u[];
    uint32_t* As_h = smem_u;
    uint32_t* As_l = smem_u + ASIZE;
    uint32_t* Bs_h = smem_u + 2 * ASIZE;
    uint32_t* Bs_l = smem_u + 2 * ASIZE + BSIZE;
    int gph = blockIdx.x, rb = blockIdx.y;
    int row0 = rb * 64;
    int tid = threadIdx.x;
    int lane = tid & 31, wid = tid >> 5;
    int g = lane >> 2, t = lane & 3, n0 = wid * 16;

#pragma unroll
    for (int it = 0; it < 16; it++) {
        int id = tid + 256 * it;
        int r = id >> 6, kp = id & 63;
        int lrow = row0 + r;
        float2 v;
        if (lrow >= NPG) v = make_float2(0.f, 0.f);
        else if (lrow == 0) {
            v = make_float2(blm[2 * kp], blm[2 * kp + 1]);
#pragma unroll
            for (int c = 0; c < NCH4; c++) {
                float2 p = *(const float2*)&d_Pc[((size_t)c * G + gph) * H + 2 * kp];
                v.x += p.x;
                v.y += p.y;
            }
        } else v = *(const float2*)&nemb[(size_t)(gph * NPG + lrow) * H + 2 * kp];
        uint32_t b, s;
        bsplit2(v.x, v.y, b, s);
        As_h[r * ASTR + kp] = b;
        As_l[r * ASTR + kp] = s;
    }
    const uint32_t* MB = d_MTBig + gph * 64 * H;
    const uint32_t* MS = d_MTSml + gph * 64 * H;
#pragma unroll
    for (int it = 0; it < 8; it++) {
        int id = tid + 256 * it;
        int hp = id >> 5, q = id & 31;
        *(uint4*)&Bs_h[hp * BSTR + q * 4] = *(const uint4*)&MB[hp * H + q * 4];
        *(uint4*)&Bs_l[hp * BSTR + q * 4] = *(const uint4*)&MS[hp * H + q * 4];
    }
    __syncthreads();

    float acc[4][2][4];
#pragma unroll
    for (int a = 0; a < 4; a++)
#pragma unroll
        for (int b = 0; b < 2; b++)
#pragma unroll
            for (int c = 0; c < 4; c++) acc[a][b][c] = 0.f;

#pragma unroll
    for (int s = 0; s < 8; s++)
        mma_step(As_h, As_l, Bs_h, Bs_l, acc, g, t, n0, s * 8);

#pragma unroll
    for (int mt = 0; mt < 4; mt++) {
#pragma unroll
        for (int nt = 0; nt < 2; nt++) {
            int col = n0 + nt * 8 + 2 * t;
            float b0 = bbil[col], b1 = bbil[col + 1];
            int lr0 = row0 + mt * 16 + g;
            if (lr0 < NPG)
                *(float2*)&d_nodes[(size_t)(gph * NPG + lr0) * H + col] =
                    make_float2(acc[mt][nt][0] + b0, acc[mt][nt][1] + b1);
            int lr1 = lr0 + 8;
            if (lr1 < NPG)
                *(float2*)&d_nodes[(size_t)(gph * NPG + lr1) * H + col] =
                    make_float2(acc[mt][nt][2] + b0, acc[mt][nt][3] + b1);
        }
    }
}

// ---------------- per-(hop, edge-type) attention scalar table --------------
__global__ void k_aet(const float* __restrict__ eemb, const float* __restrict__ linE,
                      const float* __restrict__ attE) {
    int i = blockIdx.x / NT, tt = blockIdx.x % NT;
    int c = threadIdx.x;
    const float* le = linE + (size_t)i * H * H;
    const float* em = eemb + (size_t)tt * H;
    float tmp = 0.f;
#pragma unroll 8
    for (int k = 0; k < H; k++) tmp += em[k] * le[(size_t)k * H + c];
    float v = tmp * attE[i * H + c];
    for (int o = 16; o > 0; o >>= 1) v += __shfl_xor_sync(0xffffffffu, v, o);
    __shared__ float ps[4];
    if ((threadIdx.x & 31) == 0) ps[threadIdx.x >> 5] = v;
    __syncthreads();
    if (threadIdx.x == 0) d_aet[i * NT + tt] = ps[0] + ps[1] + ps[2] + ps[3];
}

// ---------------- per-hop: h = nodes @ lin (32-row tile, reg-prefetch B) ---
#define LOADB(dh, dl, ps)                                                   \
    _Pragma("unroll") for (int nt = 0; nt < 2; nt++) {                      \
        int col = n0 + nt * 8 + g;                                          \
        dh[nt][0] = LB[(ps + t) * H + col];                                 \
        dh[nt][1] = LB[(ps + t + 4) * H + col];                             \
        dl[nt][0] = LS[(ps + t) * H + col];                                 \
        dl[nt][1] = LS[(ps + t + 4) * H + col];                             \
    }

__global__ void __launch_bounds__(256) k_lin(int hop, const float* __restrict__ att_s,
                                             const float* __restrict__ att_d) {
    __shared__ uint32_t As_h[LTM * ASTR];
    __shared__ uint32_t As_l[LTM * ASTR];
    __shared__ float sS[8 * LTM];
    __shared__ float sD[8 * LTM];
    int row0 = blockIdx.x * LTM;
    int tid = threadIdx.x;
    int lane = tid & 31, wid = tid >> 5;
    int g = lane >> 2, t = lane & 3, n0 = wid * 16;

#pragma unroll
    for (int it = 0; it < 8; it++) {
        int id = tid + 256 * it;
        int r = id >> 6, kp = id & 63;
        float2 v = *(const float2*)&d_nodes[(size_t)(row0 + r) * H + 2 * kp];
        uint32_t b, s;
        bsplit2(v.x, v.y, b, s);
        As_h[r * ASTR + kp] = b;
        As_l[r * ASTR + kp] = s;
    }
    __syncthreads();

    const uint32_t* LB = d_linBig + hop * 64 * H;
    const uint32_t* LS = d_linSml + hop * 64 * H;

    float acc[2][2][4];
#pragma unroll
    for (int a = 0; a < 2; a++)
#pragma unroll
        for (int b = 0; b < 2; b++)
#pragma unroll
            for (int c = 0; c < 4; c++) acc[a][b][c] = 0.f;

    uint32_t bh[2][2], bl[2][2];
    LOADB(bh, bl, 0)
#pragma unroll
    for (int s = 0; s < 8; s++) {
        uint32_t nh[2][2], nl[2][2];
        if (s < 7) { LOADB(nh, nl, (s + 1) * 8) }
        int ps = s * 8;
#pragma unroll
        for (int mt = 0; mt < 2; mt++) {
            int r0 = (mt * 16 + g) * ASTR, r1 = (mt * 16 + 8 + g) * ASTR;
            uint32_t ah0 = As_h[r0 + ps + t];
            uint32_t ah1 = As_h[r1 + ps + t];
            uint32_t ah2 = As_h[r0 + ps + t + 4];
            uint32_t ah3 = As_h[r1 + ps + t + 4];
            uint32_t al0 = As_l[r0 + ps + t];
            uint32_t al1 = As_l[r1 + ps + t];
            uint32_t al2 = As_l[r0 + ps + t + 4];
            uint32_t al3 = As_l[r1 + ps + t + 4];
#pragma unroll
            for (int nt = 0; nt < 2; nt++) {
                MMA4(acc[mt][nt], ah0, ah1, ah2, ah3, bh[nt][0], bh[nt][1]);
                MMA4(acc[mt][nt], al0, al1, al2, al3, bh[nt][0], bh[nt][1]);
                MMA4(acc[mt][nt], ah0, ah1, ah2, ah3, bl[nt][0], bl[nt][1]);
            }
        }
        if (s < 7) {
#pragma unroll
            for (int nt = 0; nt < 2; nt++) {
                bh[nt][0] = nh[nt][0]; bh[nt][1] = nh[nt][1];
                bl[nt][0] = nl[nt][0]; bl[nt][1] = nl[nt][1];
            }
        }
    }

#pragma unroll
    for (int mt = 0; mt < 2; mt++) {
        int row = row0 + mt * 16 + g;
#pragma unroll
        for (int nt = 0; nt < 2; nt++) {
            int col = n0 + nt * 8 + 2 * t;
            *(float2*)&d_hbuf[(size_t)row * H + col] = make_float2(acc[mt][nt][0], acc[mt][nt][1]);
            *(float2*)&d_hbuf[(size_t)(row + 8) * H + col] = make_float2(acc[mt][nt][2], acc[mt][nt][3]);
        }
    }

    float pS[2][2] = {{0.f, 0.f}, {0.f, 0.f}};
    float pD[2][2] = {{0.f, 0.f}, {0.f, 0.f}};
#pragma unroll
    for (int nt = 0; nt < 2; nt++) {
        int c0 = n0 + nt * 8 + 2 * t;
        float as0 = att_s[c0], as1 = att_s[c0 + 1];
        float ad0 = att_d[c0], ad1 = att_d[c0 + 1];
#pragma unroll
        for (int mt = 0; mt < 2; mt++) {
            pS[mt][0] += acc[mt][nt][0] * as0 + acc[mt][nt][1] * as1;
            pS[mt][1] += acc[mt][nt][2] * as0 + acc[mt][nt][3] * as1;
            pD[mt][0] += acc[mt][nt][0] * ad0 + acc[mt][nt][1] * ad1;
            pD[mt][1] += acc[mt][nt][2] * ad0 + acc[mt][nt][3] * ad1;
        }
    }
#pragma unroll
    for (int o = 1; o < 4; o <<= 1) {
#pragma unroll
        for (int mt = 0; mt < 2; mt++) {
#pragma unroll
            for (int hf = 0; hf < 2; hf++) {
                pS[mt][hf] += __shfl_xor_sync(0xffffffffu, pS[mt][hf], o);
                pD[mt][hf] += __shfl_xor_sync(0xffffffffu, pD[mt][hf], o);
            }
        }
    }
    if (t == 0) {
#pragma unroll
        for (int mt = 0; mt < 2; mt++) {
#pragma unroll
            for (int hf = 0; hf < 2; hf++) {
                int row = mt * 16 + hf * 8 + g;
                sS[wid * LTM + row] = pS[mt][hf];
                sD[wid * LTM + row] = pD[mt][hf];
            }
        }
    }
    __syncthreads();
    if (tid < 64) {
        int which = tid >> 5, row = tid & 31;
        const float* sp = which ? sD : sS;
        float s = 0.f;
#pragma unroll
        for (int w = 0; w < 8; w++) s += sp[w * LTM + row];
        if (which) d_adst[row0 + row] = s;
        else d_asrc[row0 + row] = s;
    }
}

// ---------------- per-hop: softmax attention + aggregate + gelu ------------
// 2 warps per node: phase-1 softmax duplicated (no sync); gather split in
// half per warp; partials merged via one smem exchange.
__global__ void __launch_bounds__(256, 5) k_gat(int hop, const float* __restrict__ bias,
                                                float* __restrict__ out, int last) {
    __shared__ __align__(16) int sp[8][32];
    __shared__ __align__(16) float sw[8][32];
    __shared__ __align__(16) float4 sacc[8][32];
    int wid = threadIdx.x >> 5;
    int lane = threadIdx.x & 31;
    int half = wid & 1;
    int n = blockIdx.x * 4 + (wid >> 1);
    const float* aet = d_aet + hop * NT;
    int s0 = d_rowptr[n], s1 = d_rowptr[n + 1];
    int deg = s1 - s0;
    float adn = d_adst[n];
    float asn = d_asrc[n];

    float mf, inv, ws;
    bool fast = (deg <= 32);

    if (fast) {
        int p_reg = 0;
        float lg_reg = 0.f, ae_reg = 0.f;
        if (lane < deg) {
            p_reg = d_csr[s0 + lane];
            ae_reg = aet[p_reg >> 20];
            lg_reg = lrelu(d_asrc[p_reg & 0xFFFFF] + adn + ae_reg);
        }
        float m = (lane < deg) ? lg_reg : -1e30f;
        float aes = ae_reg;
#pragma unroll
        for (int o = 16; o > 0; o >>= 1) {
            m = fmaxf(m, __shfl_xor_sync(0xffffffffu, m, o));
            aes += __shfl_xor_sync(0xffffffffu, aes, o);
        }
        float aloop = aes / (float)(deg > 0 ? deg : 1);
        float slg = lrelu(asn + adn + aloop);
        mf = fmaxf(m, slg);
        float w_reg = (lane < deg) ? __expf(lg_reg - mf) : 0.f;
        ws = __expf(slg - mf);
        sp[wid][lane] = p_reg;
        sw[wid][lane] = w_reg;
        float sf = w_reg;
#pragma unroll
        for (int o = 16; o > 0; o >>= 1)
            sf += __shfl_xor_sync(0xffffffffu, sf, o);
        sf += ws;
        inv = 1.f / sf;
        __syncwarp();
    } else {
        float m = -1e30f, s = 0.f, aes = 0.f;
        for (int e = s0 + lane; e < s1; e += 32) {
            int p = d_csr[e];
            float ae = aet[p >> 20];
            float lg = lrelu(d_asrc[p & 0xFFFFF] + adn + ae);
            d_lscr[e] = lg;  // both warps write same value (benign)
            aes += ae;
            float mn = fmaxf(m, lg);
            s = s * __expf(m - mn) + __expf(lg - mn);
            m = mn;
        }
        __syncwarp();
#pragma unroll
        for (int o = 16; o > 0; o >>= 1) {
            float mo = __shfl_xor_sync(0xffffffffu, m, o);
            float so = __shfl_xor_sync(0xffffffffu, s, o);
            aes += __shfl_xor_sync(0xffffffffu, aes, o);
            float mn = fmaxf(m, mo);
            s = s * __expf(m - mn) + so * __expf(mo - mn);
            m = mn;
        }
        float aloop = aes / (float)deg;
        float slg = lrelu(asn + adn + aloop);
        mf = fmaxf(m, slg);
        ws = __expf(slg - mf);
        float sf = s * __expf(m - mf) + ws;
        inv = 1.f / sf;
    }

    float4 a0 = make_float4(0.f, 0.f, 0.f, 0.f);
    float4 a1 = make_float4(0.f, 0.f, 0.f, 0.f);

    if (fast) {
        int dh = (deg + 1) >> 1;
        int lo = half * dh;
        int hi = lo + dh;
        if (hi > deg) hi = deg;
        int j = lo;
        for (; j + 8 <= hi; j += 8) {
            int pp[8];
            float ww[8];
            float4 hh[8];
#pragma unroll
            for (int i = 0; i < 8; i++) {
                pp[i] = sp[wid][j + i];
                ww[i] = sw[wid][j + i];
            }
#pragma unroll
            for (int i = 0; i < 8; i++)
                hh[i] = ((const float4*)(d_hbuf + (size_t)(pp[i] & 0xFFFFF) * H))[lane];
#pragma unroll
            for (int i = 0; i < 8; i++) {
                float4* a = (i & 1) ? &a1 : &a0;
                a->x += ww[i] * hh[i].x;
                a->y += ww[i] * hh[i].y;
                a->z += ww[i] * hh[i].z;
                a->w += ww[i] * hh[i].w;
            }
        }
        if (j + 4 <= hi) {
            int pp[4];
            float ww[4];
            float4 hh[4];
#pragma unroll
            for (int i = 0; i < 4; i++) {
                pp[i] = sp[wid][j + i];
                ww[i] = sw[wid][j + i];
            }
#pragma unroll
            for (int i = 0; i < 4; i++)
                hh[i] = ((const float4*)(d_hbuf + (size_t)(pp[i] & 0xFFFFF) * H))[lane];
#pragma unroll
            for (int i = 0; i < 4; i++) {
                float4* a = (i & 1) ? &a1 : &a0;
                a->x += ww[i] * hh[i].x;
                a->y += ww[i] * hh[i].y;
                a->z += ww[i] * hh[i].z;
                a->w += ww[i] * hh[i].w;
            }
            j += 4;
        }
        for (; j < hi; j++) {
            int p0 = sp[wid][j];
            float w0 = sw[wid][j];
            float4 h0 = ((const float4*)(d_hbuf + (size_t)(p0 & 0xFFFFF) * H))[lane];
            a0.x += w0 * h0.x; a0.y += w0 * h0.y;
            a0.z += w0 * h0.z; a0.w += w0 * h0.w;
        }
    } else {
        for (int e = s0 + half; e < s1; e += 2) {
            int p = d_csr[e];
            float w = __expf(d_lscr[e] - mf);
            float4 hv = ((const float4*)(d_hbuf + (size_t)(p & 0xFFFFF) * H))[lane];
            a0.x += w * hv.x; a0.y += w * hv.y;
            a0.z += w * hv.z; a0.w += w * hv.w;
        }
    }

    a0.x += a1.x; a0.y += a1.y; a0.z += a1.z; a0.w += a1.w;
    if (half == 0) {
        // self-loop contribution counted once
        float4 hn = ((const float4*)(d_hbuf + (size_t)n * H))[lane];
        a0.x += ws * hn.x;
        a0.y += ws * hn.y;
        a0.z += ws * hn.z;
        a0.w += ws * hn.w;
    } else {
        sacc[wid][lane] = a0;
    }
    __syncthreads();
    if (half == 0) {
        float4 p2 = sacc[wid + 1][lane];
        a0.x += p2.x; a0.y += p2.y; a0.z += p2.z; a0.w += p2.w;

        float4 b = ((const float4*)bias)[lane];
        float4 o;
        o.x = gelu_exact(a0.x * inv + b.x);
        o.y = gelu_exact(a0.y * inv + b.y);
        o.z = gelu_exact(a0.z * inv + b.z);
        o.w = gelu_exact(a0.w * inv + b.w);
        ((float4*)(d_nodes + (size_t)n * H))[lane] = o;
        if (last && (n % NPG == 0))
            ((float4*)(out + (size_t)(n / NPG) * H))[lane] = o;
    }
}

// ---------------- launch ----------------
extern "C" void kernel_launch(void* const* d_in, const int* in_sizes, int n_in,
                              void* d_out, int out_size) {
    (void)in_sizes; (void)n_in; (void)out_size;
    const float* lm   = (const float*)d_in[0];
    const float* nemb = (const float*)d_in[1];
    const float* Wlm  = (const float*)d_in[2];
    const float* blm  = (const float*)d_in[3];
    const float* Wbil = (const float*)d_in[4];
    const float* bbil = (const float*)d_in[5];
    const float* eemb = (const float*)d_in[6];
    const float* glin = (const float*)d_in[7];
    const float* gas  = (const float*)d_in[8];
    const float* gad  = (const float*)d_in[9];
    const float* gle  = (const float*)d_in[10];
    const float* gae  = (const float*)d_in[11];
    const float* gb   = (const float*)d_in[12];
    const int* ei     = (const int*)d_in[13];
    const int* et     = (const int*)d_in[14];
    float* out = (float*)d_out;

    cudaFuncSetAttribute(k_bil, cudaFuncAttributeMaxDynamicSharedMemorySize, BIL_SMEM);
    cudaFuncSetAttribute(k_nodes0, cudaFuncAttributeMaxDynamicSharedMemorySize, SMEM_BYTES);

    // fork/join overlap (R15 win): CSR branch hides under bilinear chain
    cudaStream_t s2;
    cudaStreamCreateWithFlags(&s2, cudaStreamNonBlocking);
    cudaEvent_t eFork, eJoin;
    cudaEventCreateWithFlags(&eFork, cudaEventDisableTiming);
    cudaEventCreateWithFlags(&eJoin, cudaEventDisableTiming);

    cudaEventRecord(eFork, 0);
    cudaStreamWaitEvent(s2, eFork, 0);

    // ---- branch B (side stream): CSR + lin-split + aet ----
    k_prepB<<<210, 256, 0, s2>>>(glin);
    k_count<<<(N_EDGES + 255) / 256, 256, 0, s2>>>(ei);
    k_scan<<<1, 1024, 0, s2>>>();
    k_scatter<<<(N_EDGES + 255) / 256, 256, 0, s2>>>(ei, et);
    k_aet<<<HOPS * NT, 128, 0, s2>>>(eemb, gle, gae);
    cudaEventRecord(eJoin, s2);

    // ---- branch A (main stream): bilinear chain ----
    k_prepA<<<128, 256>>>(lm);
    k_bil<<<dim3(H + 1, NCH4), 256, BIL_SMEM>>>(Wbil, Wlm);
    k_redT<<<dim3(G, 4, 4), dim3(32, 32)>>>();
    k_nodes0<<<dim3(G, 4), 256, SMEM_BYTES>>>(nemb, bbil, blm);
    k_lin<<<N_NODES / LTM, 256>>>(0, gas, gad);

    cudaStreamWaitEvent(0, eJoin, 0);
    k_gat<<<N_NODES / 4, 256>>>(0, gb, out, 0);

    for (int hop = 1; hop < HOPS; hop++) {
        k_lin<<<N_NODES / LTM, 256>>>(hop, gas + (size_t)hop * H,
                                      gad + (size_t)hop * H);
        k_gat<<<N_NODES / 4, 256>>>(hop, gb + (size_t)hop * H, out,
                                    hop == HOPS - 1 ? 1 : 0);
    }
}

// round 17
// speedup vs baseline: 1.1313x; 1.1313x over previous
#include <cuda_runtime.h>
#include <cuda_bf16.h>
#include <math.h>
#include <stdint.h>

#define N_NODES 12800
#define N_EDGES 128000
#define G 64
#define NPG 200
#define LMD 1024
#define H 128
#define NT 42
#define HOPS 5
#define NCH4 4
#define CHL (LMD / NCH4)

// ---- k_bil smem: quarter-range A fragments + raw B stages ----
#define AFRAG_Q (4 * 4 * 32 * 4)     // 2048 u32 (4 steps worth)
#define RSTR 132
#define RSTAGE (16 * RSTR)
#define NSTAGE 4
#define BIL_SMEM ((2 * AFRAG_Q + NSTAGE * RSTAGE) * 4)   // 50176 B

// ---- k_nodes0 smem ----
#define ASTR 68
#define BSTR 132
#define ASIZE (64 * ASTR)
#define BSIZE (64 * BSTR)
#define SMEM_BYTES ((2 * ASIZE + 2 * BSIZE) * 4)  // 102400

#define LTM 32

// ---------------- static scratch ----------------
__device__ __align__(16) float d_P[(size_t)NCH4 * H * G * H];
__device__ __align__(16) float d_Pc[(size_t)NCH4 * G * H];
__device__ __align__(16) float d_nodes[(size_t)N_NODES * H];
__device__ __align__(16) float d_hbuf[(size_t)N_NODES * H];
__device__ __align__(16) uint32_t d_lmBig[G * 512];
__device__ __align__(16) uint32_t d_lmSml[G * 512];
__device__ __align__(16) uint32_t d_linBig[HOPS * 64 * H];
__device__ __align__(16) uint32_t d_linSml[HOPS * 64 * H];
__device__ __align__(16) uint32_t d_MTBig[G * 64 * H];
__device__ __align__(16) uint32_t d_MTSml[G * 64 * H];
__device__ float d_asrc[N_NODES];
__device__ float d_adst[N_NODES];
__device__ float d_aet[HOPS * NT];
__device__ float d_lscr[N_EDGES];
__device__ int d_deg[N_NODES];
__device__ int d_rowptr[N_NODES + 1];
__device__ int d_cursor[N_NODES];
__device__ int d_csr[N_EDGES];

__device__ __forceinline__ float lrelu(float x) { return x > 0.f ? x : 0.2f * x; }
__device__ __forceinline__ float gelu_exact(float x) {
    return 0.5f * x * (1.f + erff(x * 0.70710678118654752440f));
}

__device__ __forceinline__ uint32_t bpack(float e, float o) {
    __nv_bfloat162 p = __floats2bfloat162_rn(e, o);
    return *reinterpret_cast<uint32_t*>(&p);
}
__device__ __forceinline__ float bbig(float x) {
    return __bfloat162float(__float2bfloat16_rn(x));
}
__device__ __forceinline__ void bsplit2(float v0, float v1, uint32_t& big, uint32_t& sml) {
    float b0 = bbig(v0), b1 = bbig(v1);
    big = bpack(b0, b1);
    sml = bpack(v0 - b0, v1 - b1);
}

__device__ __forceinline__ void cp16(uint32_t saddr, const void* gptr) {
    asm volatile("cp.async.ca.shared.global [%0], [%1], 16;" :: "r"(saddr), "l"(gptr));
}
__device__ __forceinline__ void cp_commit() { asm volatile("cp.async.commit_group;"); }
__device__ __forceinline__ void cp_wait2() { asm volatile("cp.async.wait_group 2;"); }

#define MMA4(C, A0, A1, A2, A3, B0, B1)                                     \
    asm volatile(                                                           \
        "mma.sync.aligned.m16n8k16.row.col.f32.bf16.bf16.f32 "              \
        "{%0,%1,%2,%3}, {%4,%5,%6,%7}, {%8,%9}, {%0,%1,%2,%3};"             \
        : "+f"(C[0]), "+f"(C[1]), "+f"(C[2]), "+f"(C[3])                    \
        : "r"(A0), "r"(A1), "r"(A2), "r"(A3), "r"(B0), "r"(B1));

// one K16 step with array-layout A/B in smem (k_nodes0)
__device__ __forceinline__ void mma_step(const uint32_t* As_h, const uint32_t* As_l,
                                         const uint32_t* Bs_h, const uint32_t* Bs_l,
                                         float acc[4][2][4], int g, int t, int n0, int ps) {
    uint32_t bh[2][2], bl[2][2];
#pragma unroll
    for (int nt = 0; nt < 2; nt++) {
        int col = n0 + nt * 8 + g;
        bh[nt][0] = Bs_h[(ps + t) * BSTR + col];
        bh[nt][1] = Bs_h[(ps + t + 4) * BSTR + col];
        bl[nt][0] = Bs_l[(ps + t) * BSTR + col];
        bl[nt][1] = Bs_l[(ps + t + 4) * BSTR + col];
    }
#pragma unroll
    for (int mt = 0; mt < 4; mt++) {
        int r0 = (mt * 16 + g) * ASTR, r1 = (mt * 16 + 8 + g) * ASTR;
        uint32_t ah0 = As_h[r0 + ps + t];
        uint32_t ah1 = As_h[r1 + ps + t];
        uint32_t ah2 = As_h[r0 + ps + t + 4];
        uint32_t ah3 = As_h[r1 + ps + t + 4];
        uint32_t al0 = As_l[r0 + ps + t];
        uint32_t al1 = As_l[r1 + ps + t];
        uint32_t al2 = As_l[r0 + ps + t + 4];
        uint32_t al3 = As_l[r1 + ps + t + 4];
#pragma unroll
        for (int nt = 0; nt < 2; nt++) {
            MMA4(acc[mt][nt], ah0, ah1, ah2, ah3, bh[nt][0], bh[nt][1]);
            MMA4(acc[mt][nt], al0, al1, al2, al3, bh[nt][0], bh[nt][1]);
            MMA4(acc[mt][nt], ah0, ah1, ah2, ah3, bl[nt][0], bl[nt][1]);
        }
    }
}

// ---------------- branch-A prep: lm split ----------------
__global__ void k_prepA(const float* __restrict__ lm) {
    int id = blockIdx.x * 256 + threadIdx.x;
    int r = id >> 9, p = id & 511;
    float2 v = *(const float2*)&lm[(size_t)r * LMD + 2 * p];
    uint32_t bb, s;
    bsplit2(v.x, v.y, bb, s);
    d_lmBig[r * 512 + p] = bb;
    d_lmSml[r * 512 + p] = s;
}

// ---------------- branch-B prep: lin split + deg zero ----------------
__global__ void k_prepB(const float* __restrict__ glin) {
    int b = blockIdx.x;
    int tid = threadIdx.x;
    if (b < 160) {
        int id = b * 256 + tid;
        int hop = id >> 13, rem = id & 8191;
        int kp = rem >> 7, h = rem & 127;
        const float* L = glin + (size_t)hop * H * H;
        float v0 = L[(size_t)(2 * kp) * H + h];
        float v1 = L[(size_t)(2 * kp + 1) * H + h];
        uint32_t bb, s;
        bsplit2(v0, v1, bb, s);
        d_linBig[id] = bb;
        d_linSml[id] = s;
    } else {
        int i = (b - 160) * 256 + tid;
        if (i < N_NODES) d_deg[i] = 0;
    }
}

// ---------------- CSR build ----------------
__global__ void k_count(const int* __restrict__ ei) {
    int e = blockIdx.x * blockDim.x + threadIdx.x;
    if (e < N_EDGES) atomicAdd(&d_deg[ei[N_EDGES + e]], 1);
}

__global__ void k_scan() {
    __shared__ int sums[1024];
    const int CH = 13;
    int t = threadIdx.x;
    int base = t * CH;
    int loc[CH];
    int s = 0;
#pragma unroll
    for (int j = 0; j < CH; j++) {
        int idx = base + j;
        int v = (idx < N_NODES) ? d_deg[idx] : 0;
        loc[j] = v;
        s += v;
    }
    sums[t] = s;
    __syncthreads();
    for (int off = 1; off < 1024; off <<= 1) {
        int v = (t >= off) ? sums[t - off] : 0;
        __syncthreads();
        sums[t] += v;
        __syncthreads();
    }
    int run = (t > 0) ? sums[t - 1] : 0;
#pragma unroll
    for (int j = 0; j < CH; j++) {
        int idx = base + j;
        if (idx < N_NODES) {
            d_rowptr[idx] = run;
            d_cursor[idx] = run;
            run += loc[j];
        }
    }
    if (t == 0) d_rowptr[N_NODES] = N_EDGES;
}

__global__ void k_scatter(const int* __restrict__ ei, const int* __restrict__ et) {
    int e = blockIdx.x * blockDim.x + threadIdx.x;
    if (e < N_EDGES) {
        int d = ei[N_EDGES + e];
        int pos = atomicAdd(&d_cursor[d], 1);
        d_csr[pos] = ei[e] | (et[e] << 20);
    }
}

// ---------------- bilinear + ctx: 4-stage pipeline, quarter A refill -------
__global__ void __launch_bounds__(256, 3) k_bil(const float* __restrict__ W,
                                                const float* __restrict__ Wlm) {
    extern __shared__ uint32_t su[];
    uint32_t* Af_h = su;
    uint32_t* Af_l = su + AFRAG_Q;
    float* raw = (float*)(su + 2 * AFRAG_Q);
    uint32_t raw_s = (uint32_t)__cvta_generic_to_shared(raw);

    int k = blockIdx.x, ch = blockIdx.y;
    int tid = threadIdx.x;
    int lane = tid & 31, wid = tid >> 5;
    int g = lane >> 2, t = lane & 3, n0 = wid * 16;

    const float* Bg = (k < H) ? (W + ((size_t)k * LMD + (size_t)ch * CHL) * H)
                              : (Wlm + (size_t)(ch * CHL) * H);

#pragma unroll
    for (int s = 0; s < NSTAGE - 1; s++) {
#pragma unroll
        for (int i = 0; i < 2; i++) {
            int id = tid + 256 * i;
            int row = id >> 5, c4 = id & 31;
            cp16(raw_s + (s * RSTAGE + row * RSTR + c4 * 4) * 4,
                 Bg + (size_t)(s * 16 + row) * H + c4 * 4);
        }
        cp_commit();
    }

    float acc[4][2][4];
#pragma unroll
    for (int a = 0; a < 4; a++)
#pragma unroll
        for (int b = 0; b < 2; b++)
#pragma unroll
            for (int c = 0; c < 4; c++) acc[a][b][c] = 0.f;

#pragma unroll 1
    for (int q = 0; q < 4; q++) {
#pragma unroll
        for (int it = 0; it < 8; it++) {
            int id = tid + 256 * it;
            int r = id >> 5, p = id & 31;
            int stepL = p >> 3, tt = p & 3, h4 = (p >> 2) & 1;
            int gg = r & 7, hb = (r >> 3) & 1, mt = r >> 4;
            int slot = ((stepL * 4 + mt) * 32 + gg * 4 + tt) * 4 + h4 * 2 + hb;
            int P = q * 32 + p;
            Af_h[slot] = d_lmBig[r * 512 + ch * 128 + P];
            Af_l[slot] = d_lmSml[r * 512 + ch * 128 + P];
        }
#pragma unroll 1
        for (int stepL = 0; stepL < 4; stepL++) {
            int step = q * 4 + stepL;
            cp_wait2();
            __syncthreads();
            if (step + NSTAGE - 1 < 16) {
                int s = step + NSTAGE - 1;
                int buf = s % NSTAGE;
#pragma unroll
                for (int i = 0; i < 2; i++) {
                    int id = tid + 256 * i;
                    int row = id >> 5, c4 = id & 31;
                    cp16(raw_s + (buf * RSTAGE + row * RSTR + c4 * 4) * 4,
                         Bg + (size_t)(s * 16 + row) * H + c4 * 4);
                }
            }
            cp_commit();

            const float* rb = raw + (step % NSTAGE) * RSTAGE;
            uint32_t bh[2][2], bl[2][2];
#pragma unroll
            for (int nt = 0; nt < 2; nt++) {
                int col = n0 + nt * 8 + g;
                bsplit2(rb[(2 * t) * RSTR + col], rb[(2 * t + 1) * RSTR + col],
                        bh[nt][0], bl[nt][0]);
                bsplit2(rb[(2 * t + 8) * RSTR + col], rb[(2 * t + 9) * RSTR + col],
                        bh[nt][1], bl[nt][1]);
            }
#pragma unroll
            for (int mt = 0; mt < 4; mt++) {
                uint4 ah = *(const uint4*)&Af_h[((stepL * 4 + mt) * 32 + lane) * 4];
                uint4 al = *(const uint4*)&Af_l[((stepL * 4 + mt) * 32 + lane) * 4];
#pragma unroll
                for (int nt = 0; nt < 2; nt++) {
                    MMA4(acc[mt][nt], ah.x, ah.y, ah.z, ah.w, bh[nt][0], bh[nt][1]);
                    MMA4(acc[mt][nt], al.x, al.y, al.z, al.w, bh[nt][0], bh[nt][1]);
                    MMA4(acc[mt][nt], ah.x, ah.y, ah.z, ah.w, bl[nt][0], bl[nt][1]);
                }
            }
            __syncthreads();
        }
    }

    float* Pp = (k < H) ? (d_P + ((size_t)(ch * H + k) * G) * H)
                        : (d_Pc + (size_t)ch * G * H);
#pragma unroll
    for (int mt = 0; mt < 4; mt++) {
        int row = mt * 16 + g;
#pragma unroll
        for (int nt = 0; nt < 2; nt++) {
            int col = n0 + nt * 8 + 2 * t;
            *(float2*)&Pp[(size_t)row * H + col] = make_float2(acc[mt][nt][0], acc[mt][nt][1]);
            *(float2*)&Pp[(size_t)(row + 8) * H + col] = make_float2(acc[mt][nt][2], acc[mt][nt][3]);
        }
    }
}

// reduce chunks + transpose + split to MT bf16 pairs [g][hp][k]
__global__ void k_redT() {
    __shared__ float tile[32][33];
    int g = blockIdx.x, kt = blockIdx.y, ht = blockIdx.z;
    int tx = threadIdx.x, ty = threadIdx.y;
    int k = kt * 32 + ty, h = ht * 32 + tx;
    size_t base = ((size_t)k * G + g) * H + h;
    float s = 0.f;
#pragma unroll
    for (int c = 0; c < NCH4; c++) s += d_P[(size_t)c * H * G * H + base];
    tile[ty][tx] = s;
    __syncthreads();
    if (ty < 16) {
        float v0 = tile[tx][2 * ty];
        float v1 = tile[tx][2 * ty + 1];
        uint32_t b, sm;
        bsplit2(v0, v1, b, sm);
        int idx = (g * 64 + ht * 16 + ty) * H + kt * 32 + tx;
        d_MTBig[idx] = b;
        d_MTSml[idx] = sm;
    }
}

// ---------------- nodes init (ctx summed inline) ----------------
__global__ void __launch_bounds__(256) k_nodes0(const float* __restrict__ nemb,
                                                const float* __restrict__ bbil,
                                                const float* __restrict__ blm) {
    extern __shared__ uint32_t smem_u[];
    uint32_t* As_h = smem_u;
    uint32_t* As_l = smem_u + ASIZE;
    uint32_t* Bs_h = smem_u + 2 * ASIZE;
    uint32_t* Bs_l = smem_u + 2 * ASIZE + BSIZE;
    int gph = blockIdx.x, rb = blockIdx.y;
    int row0 = rb * 64;
    int tid = threadIdx.x;
    int lane = tid & 31, wid = tid >> 5;
    int g = lane >> 2, t = lane & 3, n0 = wid * 16;

#pragma unroll
    for (int it = 0; it < 16; it++) {
        int id = tid + 256 * it;
        int r = id >> 6, kp = id & 63;
        int lrow = row0 + r;
        float2 v;
        if (lrow >= NPG) v = make_float2(0.f, 0.f);
        else if (lrow == 0) {
            v = make_float2(blm[2 * kp], blm[2 * kp + 1]);
#pragma unroll
            for (int c = 0; c < NCH4; c++) {
                float2 p = *(const float2*)&d_Pc[((size_t)c * G + gph) * H + 2 * kp];
                v.x += p.x;
                v.y += p.y;
            }
        } else v = *(const float2*)&nemb[(size_t)(gph * NPG + lrow) * H + 2 * kp];
        uint32_t b, s;
        bsplit2(v.x, v.y, b, s);
        As_h[r * ASTR + kp] = b;
        As_l[r * ASTR + kp] = s;
    }
    const uint32_t* MB = d_MTBig + gph * 64 * H;
    const uint32_t* MS = d_MTSml + gph * 64 * H;
#pragma unroll
    for (int it = 0; it < 8; it++) {
        int id = tid + 256 * it;
        int hp = id >> 5, q = id & 31;
        *(uint4*)&Bs_h[hp * BSTR + q * 4] = *(const uint4*)&MB[hp * H + q * 4];
        *(uint4*)&Bs_l[hp * BSTR + q * 4] = *(const uint4*)&MS[hp * H + q * 4];
    }
    __syncthreads();

    float acc[4][2][4];
#pragma unroll
    for (int a = 0; a < 4; a++)
#pragma unroll
        for (int b = 0; b < 2; b++)
#pragma unroll
            for (int c = 0; c < 4; c++) acc[a][b][c] = 0.f;

#pragma unroll
    for (int s = 0; s < 8; s++)
        mma_step(As_h, As_l, Bs_h, Bs_l, acc, g, t, n0, s * 8);

#pragma unroll
    for (int mt = 0; mt < 4; mt++) {
#pragma unroll
        for (int nt = 0; nt < 2; nt++) {
            int col = n0 + nt * 8 + 2 * t;
            float b0 = bbil[col], b1 = bbil[col + 1];
            int lr0 = row0 + mt * 16 + g;
            if (lr0 < NPG)
                *(float2*)&d_nodes[(size_t)(gph * NPG + lr0) * H + col] =
                    make_float2(acc[mt][nt][0] + b0, acc[mt][nt][1] + b1);
            int lr1 = lr0 + 8;
            if (lr1 < NPG)
                *(float2*)&d_nodes[(size_t)(gph * NPG + lr1) * H + col] =
                    make_float2(acc[mt][nt][2] + b0, acc[mt][nt][3] + b1);
        }
    }
}

// ---------------- per-(hop, edge-type) attention scalar table --------------
__global__ void k_aet(const float* __restrict__ eemb, const float* __restrict__ linE,
                      const float* __restrict__ attE) {
    int i = blockIdx.x / NT, tt = blockIdx.x % NT;
    int c = threadIdx.x;
    const float* le = linE + (size_t)i * H * H;
    const float* em = eemb + (size_t)tt * H;
    float tmp = 0.f;
#pragma unroll 8
    for (int k = 0; k < H; k++) tmp += em[k] * le[(size_t)k * H + c];
    float v = tmp * attE[i * H + c];
    for (int o = 16; o > 0; o >>= 1) v += __shfl_xor_sync(0xffffffffu, v, o);
    __shared__ float ps[4];
    if ((threadIdx.x & 31) == 0) ps[threadIdx.x >> 5] = v;
    __syncthreads();
    if (threadIdx.x == 0) d_aet[i * NT + tt] = ps[0] + ps[1] + ps[2] + ps[3];
}

// ---------------- per-hop: h = nodes @ lin (32-row tile, reg-prefetch B) ---
#define LOADB(dh, dl, ps)                                                   \
    _Pragma("unroll") for (int nt = 0; nt < 2; nt++) {                      \
        int col = n0 + nt * 8 + g;                                          \
        dh[nt][0] = LB[(ps + t) * H + col];                                 \
        dh[nt][1] = LB[(ps + t + 4) * H + col];                             \
        dl[nt][0] = LS[(ps + t) * H + col];                                 \
        dl[nt][1] = LS[(ps + t + 4) * H + col];                             \
    }

__global__ void __launch_bounds__(256) k_lin(int hop, const float* __restrict__ att_s,
                                             const float* __restrict__ att_d) {
    __shared__ uint32_t As_h[LTM * ASTR];
    __shared__ uint32_t As_l[LTM * ASTR];
    __shared__ float sS[8 * LTM];
    __shared__ float sD[8 * LTM];
    int row0 = blockIdx.x * LTM;
    int tid = threadIdx.x;
    int lane = tid & 31, wid = tid >> 5;
    int g = lane >> 2, t = lane & 3, n0 = wid * 16;

#pragma unroll
    for (int it = 0; it < 8; it++) {
        int id = tid + 256 * it;
        int r = id >> 6, kp = id & 63;
        float2 v = *(const float2*)&d_nodes[(size_t)(row0 + r) * H + 2 * kp];
        uint32_t b, s;
        bsplit2(v.x, v.y, b, s);
        As_h[r * ASTR + kp] = b;
        As_l[r * ASTR + kp] = s;
    }
    __syncthreads();

    const uint32_t* LB = d_linBig + hop * 64 * H;
    const uint32_t* LS = d_linSml + hop * 64 * H;

    float acc[2][2][4];
#pragma unroll
    for (int a = 0; a < 2; a++)
#pragma unroll
        for (int b = 0; b < 2; b++)
#pragma unroll
            for (int c = 0; c < 4; c++) acc[a][b][c] = 0.f;

    uint32_t bh[2][2], bl[2][2];
    LOADB(bh, bl, 0)
#pragma unroll
    for (int s = 0; s < 8; s++) {
        uint32_t nh[2][2], nl[2][2];
        if (s < 7) { LOADB(nh, nl, (s + 1) * 8) }
        int ps = s * 8;
#pragma unroll
        for (int mt = 0; mt < 2; mt++) {
            int r0 = (mt * 16 + g) * ASTR, r1 = (mt * 16 + 8 + g) * ASTR;
            uint32_t ah0 = As_h[r0 + ps + t];
            uint32_t ah1 = As_h[r1 + ps + t];
            uint32_t ah2 = As_h[r0 + ps + t + 4];
            uint32_t ah3 = As_h[r1 + ps + t + 4];
            uint32_t al0 = As_l[r0 + ps + t];
            uint32_t al1 = As_l[r1 + ps + t];
            uint32_t al2 = As_l[r0 + ps + t + 4];
            uint32_t al3 = As_l[r1 + ps + t + 4];
#pragma unroll
            for (int nt = 0; nt < 2; nt++) {
                MMA4(acc[mt][nt], ah0, ah1, ah2, ah3, bh[nt][0], bh[nt][1]);
                MMA4(acc[mt][nt], al0, al1, al2, al3, bh[nt][0], bh[nt][1]);
                MMA4(acc[mt][nt], ah0, ah1, ah2, ah3, bl[nt][0], bl[nt][1]);
            }
        }
        if (s < 7) {
#pragma unroll
            for (int nt = 0; nt < 2; nt++) {
                bh[nt][0] = nh[nt][0]; bh[nt][1] = nh[nt][1];
                bl[nt][0] = nl[nt][0]; bl[nt][1] = nl[nt][1];
            }
        }
    }

#pragma unroll
    for (int mt = 0; mt < 2; mt++) {
        int row = row0 + mt * 16 + g;
#pragma unroll
        for (int nt = 0; nt < 2; nt++) {
            int col = n0 + nt * 8 + 2 * t;
            *(float2*)&d_hbuf[(size_t)row * H + col] = make_float2(acc[mt][nt][0], acc[mt][nt][1]);
            *(float2*)&d_hbuf[(size_t)(row + 8) * H + col] = make_float2(acc[mt][nt][2], acc[mt][nt][3]);
        }
    }

    float pS[2][2] = {{0.f, 0.f}, {0.f, 0.f}};
    float pD[2][2] = {{0.f, 0.f}, {0.f, 0.f}};
#pragma unroll
    for (int nt = 0; nt < 2; nt++) {
        int c0 = n0 + nt * 8 + 2 * t;
        float as0 = att_s[c0], as1 = att_s[c0 + 1];
        float ad0 = att_d[c0], ad1 = att_d[c0 + 1];
#pragma unroll
        for (int mt = 0; mt < 2; mt++) {
            pS[mt][0] += acc[mt][nt][0] * as0 + acc[mt][nt][1] * as1;
            pS[mt][1] += acc[mt][nt][2] * as0 + acc[mt][nt][3] * as1;
            pD[mt][0] += acc[mt][nt][0] * ad0 + acc[mt][nt][1] * ad1;
            pD[mt][1] += acc[mt][nt][2] * ad0 + acc[mt][nt][3] * ad1;
        }
    }
#pragma unroll
    for (int o = 1; o < 4; o <<= 1) {
#pragma unroll
        for (int mt = 0; mt < 2; mt++) {
#pragma unroll
            for (int hf = 0; hf < 2; hf++) {
                pS[mt][hf] += __shfl_xor_sync(0xffffffffu, pS[mt][hf], o);
                pD[mt][hf] += __shfl_xor_sync(0xffffffffu, pD[mt][hf], o);
            }
        }
    }
    if (t == 0) {
#pragma unroll
        for (int mt = 0; mt < 2; mt++) {
#pragma unroll
            for (int hf = 0; hf < 2; hf++) {
                int row = mt * 16 + hf * 8 + g;
                sS[wid * LTM + row] = pS[mt][hf];
                sD[wid * LTM + row] = pD[mt][hf];
            }
        }
    }
    __syncthreads();
    if (tid < 64) {
        int which = tid >> 5, row = tid & 31;
        const float* sp = which ? sD : sS;
        float s = 0.f;
#pragma unroll
        for (int w = 0; w < 8; w++) s += sp[w * LTM + row];
        if (which) d_adst[row0 + row] = s;
        else d_asrc[row0 + row] = s;
    }
}

// ---------------- per-hop: softmax attention + aggregate + gelu ------------
// R15 version: 1 warp per node, max-first softmax, smem-staged gather.
__global__ void __launch_bounds__(256, 5) k_gat(int hop, const float* __restrict__ bias,
                                                float* __restrict__ out, int last) {
    __shared__ __align__(16) int sp[8][32];
    __shared__ __align__(16) float sw[8][32];
    int wid = threadIdx.x >> 5;
    int n = blockIdx.x * 8 + wid;
    int lane = threadIdx.x & 31;
    const float* aet = d_aet + hop * NT;
    int s0 = d_rowptr[n], s1 = d_rowptr[n + 1];
    int deg = s1 - s0;
    float adn = d_adst[n];
    float asn = d_asrc[n];

    float mf, inv, ws;
    bool fast = (deg <= 32);

    if (fast) {
        int p_reg = 0;
        float lg_reg = 0.f, ae_reg = 0.f;
        if (lane < deg) {
            p_reg = d_csr[s0 + lane];
            ae_reg = aet[p_reg >> 20];
            lg_reg = lrelu(d_asrc[p_reg & 0xFFFFF] + adn + ae_reg);
        }
        float m = (lane < deg) ? lg_reg : -1e30f;
        float aes = ae_reg;
#pragma unroll
        for (int o = 16; o > 0; o >>= 1) {
            m = fmaxf(m, __shfl_xor_sync(0xffffffffu, m, o));
            aes += __shfl_xor_sync(0xffffffffu, aes, o);
        }
        float aloop = aes / (float)(deg > 0 ? deg : 1);
        float slg = lrelu(asn + adn + aloop);
        mf = fmaxf(m, slg);
        float w_reg = (lane < deg) ? __expf(lg_reg - mf) : 0.f;
        ws = __expf(slg - mf);
        sp[wid][lane] = p_reg;
        sw[wid][lane] = w_reg;
        float sf = w_reg;
#pragma unroll
        for (int o = 16; o > 0; o >>= 1)
            sf += __shfl_xor_sync(0xffffffffu, sf, o);
        sf += ws;
        inv = 1.f / sf;
        __syncwarp();
    } else {
        float m = -1e30f, s = 0.f, aes = 0.f;
        for (int e = s0 + lane; e < s1; e += 32) {
            int p = d_csr[e];
            float ae = aet[p >> 20];
            float lg = lrelu(d_asrc[p & 0xFFFFF] + adn + ae);
            d_lscr[e] = lg;
            aes += ae;
            float mn = fmaxf(m, lg);
            s = s * __expf(m - mn) + __expf(lg - mn);
            m = mn;
        }
        __syncwarp();
#pragma unroll
        for (int o = 16; o > 0; o >>= 1) {
            float mo = __shfl_xor_sync(0xffffffffu, m, o);
            float so = __shfl_xor_sync(0xffffffffu, s, o);
            aes += __shfl_xor_sync(0xffffffffu, aes, o);
            float mn = fmaxf(m, mo);
            s = s * __expf(m - mn) + so * __expf(mo - mn);
            m = mn;
        }
        float aloop = aes / (float)deg;
        float slg = lrelu(asn + adn + aloop);
        mf = fmaxf(m, slg);
        ws = __expf(slg - mf);
        float sf = s * __expf(m - mf) + ws;
        inv = 1.f / sf;
    }

    float4 a0 = make_float4(0.f, 0.f, 0.f, 0.f);
    float4 a1 = make_float4(0.f, 0.f, 0.f, 0.f);

    if (fast) {
        int j = 0;
        for (; j + 8 <= deg; j += 8) {
            int4 pA = *(const int4*)&sp[wid][j];
            int4 pB = *(const int4*)&sp[wid][j + 4];
            float4 wA = *(const float4*)&sw[wid][j];
            float4 wB = *(const float4*)&sw[wid][j + 4];
            float4 h0 = ((const float4*)(d_hbuf + (size_t)(pA.x & 0xFFFFF) * H))[lane];
            float4 h1 = ((const float4*)(d_hbuf + (size_t)(pA.y & 0xFFFFF) * H))[lane];
            float4 h2 = ((const float4*)(d_hbuf + (size_t)(pA.z & 0xFFFFF) * H))[lane];
            float4 h3 = ((const float4*)(d_hbuf + (size_t)(pA.w & 0xFFFFF) * H))[lane];
            float4 h4 = ((const float4*)(d_hbuf + (size_t)(pB.x & 0xFFFFF) * H))[lane];
            float4 h5 = ((const float4*)(d_hbuf + (size_t)(pB.y & 0xFFFFF) * H))[lane];
            float4 h6 = ((const float4*)(d_hbuf + (size_t)(pB.z & 0xFFFFF) * H))[lane];
            float4 h7 = ((const float4*)(d_hbuf + (size_t)(pB.w & 0xFFFFF) * H))[lane];
            a0.x += wA.x * h0.x; a0.y += wA.x * h0.y; a0.z += wA.x * h0.z; a0.w += wA.x * h0.w;
            a1.x += wA.y * h1.x; a1.y += wA.y * h1.y; a1.z += wA.y * h1.z; a1.w += wA.y * h1.w;
            a0.x += wA.z * h2.x; a0.y += wA.z * h2.y; a0.z += wA.z * h2.z; a0.w += wA.z * h2.w;
            a1.x += wA.w * h3.x; a1.y += wA.w * h3.y; a1.z += wA.w * h3.z; a1.w += wA.w * h3.w;
            a0.x += wB.x * h4.x; a0.y += wB.x * h4.y; a0.z += wB.x * h4.z; a0.w += wB.x * h4.w;
            a1.x += wB.y * h5.x; a1.y += wB.y * h5.y; a1.z += wB.y * h5.z; a1.w += wB.y * h5.w;
            a0.x += wB.z * h6.x; a0.y += wB.z * h6.y; a0.z += wB.z * h6.z; a0.w += wB.z * h6.w;
            a1.x += wB.w * h7.x; a1.y += wB.w * h7.y; a1.z += wB.w * h7.z; a1.w += wB.w * h7.w;
        }
        if (j + 4 <= deg) {
            int4 pA = *(const int4*)&sp[wid][j];
            float4 wA = *(const float4*)&sw[wid][j];
            float4 h0 = ((const float4*)(d_hbuf + (size_t)(pA.x & 0xFFFFF) * H))[lane];
            float4 h1 = ((const float4*)(d_hbuf + (size_t)(pA.y & 0xFFFFF) * H))[lane];
            float4 h2 = ((const float4*)(d_hbuf + (size_t)(pA.z & 0xFFFFF) * H))[lane];
            float4 h3 = ((const float4*)(d_hbuf + (size_t)(pA.w & 0xFFFFF) * H))[lane];
            a0.x += wA.x * h0.x; a0.y += wA.x * h0.y; a0.z += wA.x * h0.z; a0.w += wA.x * h0.w;
            a1.x += wA.y * h1.x; a1.y += wA.y * h1.y; a1.z += wA.y * h1.z; a1.w += wA.y * h1.w;
            a0.x += wA.z * h2.x; a0.y += wA.z * h2.y; a0.z += wA.z * h2.z; a0.w += wA.z * h2.w;
            a1.x += wA.w * h3.x; a1.y += wA.w * h3.y; a1.z += wA.w * h3.z; a1.w += wA.w * h3.w;
            j += 4;
        }
        for (; j < deg; j++) {
            int p0 = sp[wid][j];
            float w0 = sw[wid][j];
            float4 h0 = ((const float4*)(d_hbuf + (size_t)(p0 & 0xFFFFF) * H))[lane];
            a0.x += w0 * h0.x; a0.y += w0 * h0.y;
            a0.z += w0 * h0.z; a0.w += w0 * h0.w;
        }
    } else {
        for (int e = s0; e < s1; ++e) {
            int p = d_csr[e];
            float w = __expf(d_lscr[e] - mf);
            float4 hv = ((const float4*)(d_hbuf + (size_t)(p & 0xFFFFF) * H))[lane];
            a0.x += w * hv.x; a0.y += w * hv.y;
            a0.z += w * hv.z; a0.w += w * hv.w;
        }
    }

    float4 hn = ((const float4*)(d_hbuf + (size_t)n * H))[lane];
    a0.x += a1.x + ws * hn.x;
    a0.y += a1.y + ws * hn.y;
    a0.z += a1.z + ws * hn.z;
    a0.w += a1.w + ws * hn.w;

    float4 b = ((const float4*)bias)[lane];
    float4 o;
    o.x = gelu_exact(a0.x * inv + b.x);
    o.y = gelu_exact(a0.y * inv + b.y);
    o.z = gelu_exact(a0.z * inv + b.z);
    o.w = gelu_exact(a0.w * inv + b.w);
    ((float4*)(d_nodes + (size_t)n * H))[lane] = o;
    if (last && (n % NPG == 0))
        ((float4*)(out + (size_t)(n / NPG) * H))[lane] = o;
}

// ---------------- launch ----------------
extern "C" void kernel_launch(void* const* d_in, const int* in_sizes, int n_in,
                              void* d_out, int out_size) {
    (void)in_sizes; (void)n_in; (void)out_size;
    const float* lm   = (const float*)d_in[0];
    const float* nemb = (const float*)d_in[1];
    const float* Wlm  = (const float*)d_in[2];
    const float* blm  = (const float*)d_in[3];
    const float* Wbil = (const float*)d_in[4];
    const float* bbil = (const float*)d_in[5];
    const float* eemb = (const float*)d_in[6];
    const float* glin = (const float*)d_in[7];
    const float* gas  = (const float*)d_in[8];
    const float* gad  = (const float*)d_in[9];
    const float* gle  = (const float*)d_in[10];
    const float* gae  = (const float*)d_in[11];
    const float* gb   = (const float*)d_in[12];
    const int* ei     = (const int*)d_in[13];
    const int* et     = (const int*)d_in[14];
    float* out = (float*)d_out;

    cudaFuncSetAttribute(k_bil, cudaFuncAttributeMaxDynamicSharedMemorySize, BIL_SMEM);
    cudaFuncSetAttribute(k_nodes0, cudaFuncAttributeMaxDynamicSharedMemorySize, SMEM_BYTES);

    // fork/join overlap (R15 win): CSR branch hides under bilinear chain
    cudaStream_t s2;
    cudaStreamCreateWithFlags(&s2, cudaStreamNonBlocking);
    cudaEvent_t eFork, eJoin;
    cudaEventCreateWithFlags(&eFork, cudaEventDisableTiming);
    cudaEventCreateWithFlags(&eJoin, cudaEventDisableTiming);

    cudaEventRecord(eFork, 0);
    cudaStreamWaitEvent(s2, eFork, 0);

    // ---- branch B (side stream): CSR + lin-split + aet ----
    k_prepB<<<210, 256, 0, s2>>>(glin);
    k_count<<<(N_EDGES + 255) / 256, 256, 0, s2>>>(ei);
    k_scan<<<1, 1024, 0, s2>>>();
    k_scatter<<<(N_EDGES + 255) / 256, 256, 0, s2>>>(ei, et);
    k_aet<<<HOPS * NT, 128, 0, s2>>>(eemb, gle, gae);
    cudaEventRecord(eJoin, s2);

    // ---- branch A (main stream): bilinear chain ----
    k_prepA<<<128, 256>>>(lm);
    k_bil<<<dim3(H + 1, NCH4), 256, BIL_SMEM>>>(Wbil, Wlm);
    k_redT<<<dim3(G, 4, 4), dim3(32, 32)>>>();
    k_nodes0<<<dim3(G, 4), 256, SMEM_BYTES>>>(nemb, bbil, blm);
    k_lin<<<N_NODES / LTM, 256>>>(0, gas, gad);

    cudaStreamWaitEvent(0, eJoin, 0);
    k_gat<<<N_NODES / 8, 256>>>(0, gb, out, 0);

    for (int hop = 1; hop < HOPS; hop++) {
        k_lin<<<N_NODES / LTM, 256>>>(hop, gas + (size_t)hop * H,
                                      gad + (size_t)hop * H);
        k_gat<<<N_NODES / 8, 256>>>(hop, gb + (size_t)hop * H, out,
                                    hop == HOPS - 1 ? 1 : 0);
    }
}